// round 13
// baseline (speedup 1.0000x reference)
#include <cuda_runtime.h>
#include <cuda_fp16.h>
#include <stdint.h>

// ---------------------------------------------------------------------------
// TopK Router, R13: single-pass fp16 HMMA GEMM, deep cp.async x pipeline,
// 2 consumer warps per SMSP (8 consumers x 32rows/32experts + 4 producers),
// + warp-per-row exact contender re-ranking.
// logits = x @ W^T : [16384, 64], softmax, top-2.
// out f32: probs[16384*64] ++ indices[16384*2] ++ values[16384*2]
// ---------------------------------------------------------------------------

#define D_DIM   4096
#define E_DIM   64
#define NROWS   16384
#define ROWS_PER_BLK 128
#define THREADS 384
#define KC      64
#define NCHUNK  (D_DIM / KC)

#define GAP_T    4e-3f
#define BAND_MUL 0.9940180f    // exp(-6e-3)

// smem layout (bytes)
#define XS_SLOT   (ROWS_PER_BLK * 68 * 4)    // 34816 B
#define SM_XS(s)  ((s) * XS_SLOT)            // 3 slots
#define A_TILE    (ROWS_PER_BLK * 128)       // 16384 B
#define SM_A(b)   (3 * XS_SLOT + (b) * A_TILE)
#define W_TILE    (E_DIM * 128)              // 8192 B
#define SM_W(s)   (3 * XS_SLOT + 2 * A_TILE + (s) * W_TILE)   // 4 slots
#define SMEM_BYTES (3 * XS_SLOT + 2 * A_TILE + 4 * W_TILE)    // 169984

#define LG_STRIDE 68

#define SWZ(o) ((o) ^ (((o) >> 3) & 0x70))

__device__ __half g_Whi[E_DIM * D_DIM];
__device__ int    g_ncand;
__device__ int    g_cand[NROWS];

// ---------------- PTX helpers -----------------------------------------------
__device__ __forceinline__ void cp16(uint32_t dst, const void* src) {
    asm volatile("cp.async.cg.shared.global [%0], [%1], 16;" :: "r"(dst), "l"(src));
}
__device__ __forceinline__ void cp_commit() {
    asm volatile("cp.async.commit_group;");
}
__device__ __forceinline__ void cp_wait1() {
    asm volatile("cp.async.wait_group 1;" ::: "memory");
}
__device__ __forceinline__ void cp_wait0() {
    asm volatile("cp.async.wait_group 0;" ::: "memory");
}
__device__ __forceinline__ void ldsm4(uint32_t addr, uint32_t* r) {
    asm volatile("ldmatrix.sync.aligned.m8n8.x4.shared.b16 {%0,%1,%2,%3}, [%4];"
                 : "=r"(r[0]), "=r"(r[1]), "=r"(r[2]), "=r"(r[3]) : "r"(addr));
}
__device__ __forceinline__ void mma16816(float* c,
                                         const uint32_t* a,
                                         uint32_t b0, uint32_t b1) {
    asm volatile(
        "mma.sync.aligned.m16n8k16.row.col.f32.f16.f16.f32 "
        "{%0,%1,%2,%3}, {%4,%5,%6,%7}, {%8,%9}, {%0,%1,%2,%3};"
        : "+f"(c[0]), "+f"(c[1]), "+f"(c[2]), "+f"(c[3])
        : "r"(a[0]), "r"(a[1]), "r"(a[2]), "r"(a[3]), "r"(b0), "r"(b1));
}

// ---------------- prep kernel -------------------------------------------------
__global__ void prep_W(const float* __restrict__ W) {
    int i = blockIdx.x * blockDim.x + threadIdx.x;
    if (i == 0) g_ncand = 0;
    g_Whi[i] = __float2half_rn(W[i] * 64.0f);
}

// ---------------- producer helpers (pt in [0,128)) ----------------------------
__device__ __forceinline__ void cpXW_chunk(uint32_t sbase, const float* __restrict__ x,
                                           int row0, int c, int pt) {
    const int slot  = c % 3;
    const int wslot = c % 4;
    const int c0 = c * KC;
#pragma unroll
    for (int it = 0; it < 16; ++it) {
        int id = it * 128 + pt;
        int row = id >> 4, seg = id & 15;
        uint32_t dst = sbase + SM_XS(slot) + (uint32_t)(row * 272 + seg * 16);
        cp16(dst, x + (size_t)(row0 + row) * D_DIM + c0 + seg * 4);
    }
#pragma unroll
    for (int it = 0; it < 4; ++it) {
        int id = it * 128 + pt;
        int e = id >> 3, q = id & 7;
        uint32_t dst = sbase + SM_W(wslot) + SWZ(e * 128 + q * 16);
        cp16(dst, g_Whi + (size_t)e * D_DIM + c0 + q * 8);
    }
    cp_commit();
}

__device__ __forceinline__ void convert_chunk(char* smem, int c, int pt) {
    const float* xs = (const float*)(smem + SM_XS(c % 3));
    char* dst = smem + SM_A(c & 1);
#pragma unroll
    for (int it = 0; it < 8; ++it) {
        int id = it * 128 + pt;
        int row = id >> 3, g = id & 7;
        const float* p = xs + row * 68 + g * 8;
        float4 a = *(const float4*)p;
        float4 b = *(const float4*)(p + 4);
        __half2 h0 = __floats2half2_rn(a.x * 16.0f, a.y * 16.0f);
        __half2 h1 = __floats2half2_rn(a.z * 16.0f, a.w * 16.0f);
        __half2 h2 = __floats2half2_rn(b.x * 16.0f, b.y * 16.0f);
        __half2 h3 = __floats2half2_rn(b.z * 16.0f, b.w * 16.0f);
        uint32_t off = SWZ(row * 128 + g * 16);
        *(uint4*)(dst + off) = make_uint4(
            *reinterpret_cast<uint32_t*>(&h0), *reinterpret_cast<uint32_t*>(&h1),
            *reinterpret_cast<uint32_t*>(&h2), *reinterpret_cast<uint32_t*>(&h3));
    }
}

// ---------------- main kernel -------------------------------------------------
__global__ void __launch_bounds__(THREADS, 1)
router_kernel(const float* __restrict__ x, float* __restrict__ out)
{
    extern __shared__ char smem[];
    const int t    = threadIdx.x;
    const int lane = t & 31;
    const int row0 = blockIdx.x * ROWS_PER_BLK;
    const uint32_t sbase = (uint32_t)__cvta_generic_to_shared(smem);
    const bool consumer = (t < 256);

    const int lg = lane >> 3;
    const int li = lane & 7;

    // consumer tile: rows [32*rowg, +32), experts [32*eh, +32)
    const int wc   = t >> 5;       // 0..7 consumers
    const int rowg = wc & 3;
    const int eh   = wc >> 2;

    float acc[2][4][4];
#pragma unroll
    for (int m = 0; m < 2; ++m)
#pragma unroll
        for (int j = 0; j < 4; ++j)
#pragma unroll
            for (int q = 0; q < 4; ++q) acc[m][j][q] = 0.f;

    uint32_t aoffb[2];
#pragma unroll
    for (int m = 0; m < 2; ++m) {
        int arow = 32 * rowg + 16 * m + li + ((lg & 1) ? 8 : 0);
        aoffb[m] = (uint32_t)(arow * 128 + ((lg & 2) ? 16 : 0));
    }
    const int berow = li + ((lg & 2) ? 8 : 0);
    uint32_t boffb[2];
#pragma unroll
    for (int p = 0; p < 2; ++p)
        boffb[p] = (uint32_t)((32 * eh + 16 * p + berow) * 128 + ((lg & 1) ? 16 : 0));

    const int pt = t - 256;

    // ---- prologue (producers) ----
    if (!consumer) {
        cpXW_chunk(sbase, x, row0, 0, pt);   // G0
        cpXW_chunk(sbase, x, row0, 1, pt);   // G1
        cp_wait1();                          // G0 done
    }
    __syncthreads();
    if (!consumer) {
        convert_chunk(smem, 0, pt);          // A0
        cpXW_chunk(sbase, x, row0, 2, pt);   // G2
        cp_wait1();                          // G1 done
    }
    __syncthreads();

    // ---- main loop ----
    for (int c = 0; c < NCHUNK; ++c) {
        if (consumer) {
            const uint32_t ahi = sbase + SM_A(c & 1);
            const uint32_t whi = sbase + SM_W(c % 4);

#pragma unroll
            for (int s = 0; s < 4; ++s) {
                uint32_t fa[2][4];
#pragma unroll
                for (int m = 0; m < 2; ++m)
                    ldsm4(ahi + SWZ(aoffb[m] + s * 32), fa[m]);
                uint32_t fw[2][4];
#pragma unroll
                for (int p = 0; p < 2; ++p)
                    ldsm4(whi + SWZ(boffb[p] + s * 32), fw[p]);
#pragma unroll
                for (int p = 0; p < 2; ++p)
#pragma unroll
                    for (int m = 0; m < 2; ++m) {
                        mma16816(acc[m][2 * p],     fa[m], fw[p][0], fw[p][1]);
                        mma16816(acc[m][2 * p + 1], fa[m], fw[p][2], fw[p][3]);
                    }
            }
        } else {
            if (c + 1 < NCHUNK) convert_chunk(smem, c + 1, pt);
            if (c + 3 < NCHUNK) {
                cpXW_chunk(sbase, x, row0, c + 3, pt);
                cp_wait1();
            } else {
                cp_wait0();
            }
        }
        __syncthreads();
    }

    // ---- epilogue: logits -> smem (reuse XS region) ----
    float* lgm = (float*)smem;
    if (consumer) {
        const int r_in = lane >> 2;
        const int col  = 2 * (lane & 3);
        const float sc = 1.0f / 1024.0f;
#pragma unroll
        for (int m = 0; m < 2; ++m) {
            const int rb = 32 * rowg + 16 * m + r_in;
#pragma unroll
            for (int j = 0; j < 4; ++j) {
                const int ce = 32 * eh + 8 * j + col;
                *(float2*)(lgm + rb * LG_STRIDE + ce)
                    = make_float2(acc[m][j][0] * sc, acc[m][j][1] * sc);
                *(float2*)(lgm + (rb + 8) * LG_STRIDE + ce)
                    = make_float2(acc[m][j][2] * sc, acc[m][j][3] * sc);
            }
        }
    }
    __syncthreads();

    if (t < ROWS_PER_BLK) {
        float l[64];
#pragma unroll
        for (int j = 0; j < 16; ++j) {
            float4 v = *(const float4*)(lgm + t * LG_STRIDE + 4 * j);
            l[4*j+0] = v.x; l[4*j+1] = v.y; l[4*j+2] = v.z; l[4*j+3] = v.w;
        }

        float mx = l[0];
#pragma unroll
        for (int j = 1; j < 64; ++j) mx = fmaxf(mx, l[j]);

        float v1 = -3.4e38f, v2 = -3.4e38f, v3 = -3.4e38f;
        int   i1 = 0,        i2 = 0;
#pragma unroll
        for (int j = 0; j < 64; ++j) {
            float lj = l[j];
            if (lj > v1)      { v3 = v2; v2 = v1; i2 = i1; v1 = lj; i1 = j; }
            else if (lj > v2) { v3 = v2; v2 = lj; i2 = j; }
            else if (lj > v3) { v3 = lj; }
        }

        float p[64], s = 0.f;
#pragma unroll
        for (int j = 0; j < 64; ++j) { p[j] = __expf(l[j] - mx); s += p[j]; }
        float inv = __fdividef(1.0f, s);

        const int grow = row0 + t;
        float* po = out + (size_t)grow * 64;
#pragma unroll
        for (int j = 0; j < 16; ++j) {
            float4 v;
            v.x = p[4*j+0] * inv; v.y = p[4*j+1] * inv;
            v.z = p[4*j+2] * inv; v.w = p[4*j+3] * inv;
            *(float4*)(po + 4 * j) = v;
        }
        float* io = out + (size_t)NROWS * 64;
        io[(size_t)grow * 2 + 0] = (float)i1;
        io[(size_t)grow * 2 + 1] = (float)i2;
        float* vo = out + (size_t)NROWS * 64 + (size_t)NROWS * 2;
        vo[(size_t)grow * 2 + 0] = __expf(v1 - mx) * inv;
        vo[(size_t)grow * 2 + 1] = __expf(v2 - mx) * inv;

        if ((v1 - v2) < GAP_T || (v2 - v3) < GAP_T) {
            int slot = atomicAdd(&g_ncand, 1);
            g_cand[slot] = grow;
        }
    }
}

// ---------------- fixup: one warp per flagged row ------------------------------
__global__ void __launch_bounds__(256, 1)
fixup_kernel(const float* __restrict__ x, const float* __restrict__ W,
             float* __restrict__ out)
{
    const int n    = g_ncand;
    const int lane = threadIdx.x & 31;
    const int gw   = (blockIdx.x * blockDim.x + threadIdx.x) >> 5;
    const int nw   = (gridDim.x * blockDim.x) >> 5;

    for (int ci = gw; ci < n; ci += nw) {
        const int row = g_cand[ci];
        const float* probs = out + (size_t)row * 64;

        float p0 = probs[lane];
        float p1 = probs[lane + 32];

        float m1 = fmaxf(p0, p1), m2 = fminf(p0, p1);
#pragma unroll
        for (int o = 16; o > 0; o >>= 1) {
            float o1 = __shfl_xor_sync(0xFFFFFFFF, m1, o);
            float o2 = __shfl_xor_sync(0xFFFFFFFF, m2, o);
            float n1 = fmaxf(m1, o1);
            float n2 = fminf(fmaxf(m1, o2), fmaxf(o1, m2));
            n2 = fmaxf(n2, fminf(m1, o1));
            m1 = n1; m2 = n2;
        }
        const float thresh = m2 * BAND_MUL;

        unsigned b0 = __ballot_sync(0xFFFFFFFF, p0 >= thresh);
        unsigned b1 = __ballot_sync(0xFFFFFFFF, p1 >= thresh);

        const float4* xr = (const float4*)(x + (size_t)row * D_DIM);

        float best1 = -3.4e38f, best2 = -3.4e38f;
        int   bi1 = -1,         bi2 = -1;

        for (int e = 0; e < 64; ++e) {
            bool cand = (e < 32) ? ((b0 >> e) & 1u) : ((b1 >> (e - 32)) & 1u);
            if (!cand) continue;
            const float4* wr = (const float4*)(W + (size_t)e * D_DIM);
            float a0 = 0.f, a1 = 0.f;
            for (int i = lane; i < D_DIM / 4; i += 64) {
                float4 xv = xr[i],      wv = wr[i];
                float4 xu = xr[i + 32], wu = wr[i + 32];
                a0 += xv.x * wv.x; a0 += xv.y * wv.y;
                a0 += xv.z * wv.z; a0 += xv.w * wv.w;
                a1 += xu.x * wu.x; a1 += xu.y * wu.y;
                a1 += xu.z * wu.z; a1 += xu.w * wu.w;
            }
            float a = a0 + a1;
#pragma unroll
            for (int o = 16; o > 0; o >>= 1)
                a += __shfl_xor_sync(0xFFFFFFFF, a, o);
            if (a > best1)      { best2 = best1; bi2 = bi1; best1 = a; bi1 = e; }
            else if (a > best2) { best2 = a; bi2 = e; }
        }

        if (lane == 0) {
            float* io = out + (size_t)NROWS * 64;
            io[(size_t)row * 2 + 0] = (float)bi1;
            io[(size_t)row * 2 + 1] = (float)bi2;
            float* vo = out + (size_t)NROWS * 64 + (size_t)NROWS * 2;
            vo[(size_t)row * 2 + 0] = probs[bi1];
            vo[(size_t)row * 2 + 1] = probs[bi2];
        }
    }
}

// ---------------------------------------------------------------------------
extern "C" void kernel_launch(void* const* d_in, const int* in_sizes, int n_in,
                              void* d_out, int out_size) {
    const float* x = (const float*)d_in[0];
    const float* W = (const float*)d_in[1];
    float* out = (float*)d_out;

    prep_W<<<(E_DIM * D_DIM) / 256, 256>>>(W);

    cudaFuncSetAttribute(router_kernel,
                         cudaFuncAttributeMaxDynamicSharedMemorySize, SMEM_BYTES);
    router_kernel<<<NROWS / ROWS_PER_BLK, THREADS, SMEM_BYTES>>>(x, out);

    fixup_kernel<<<256, 256>>>(x, W, out);
}

// round 14
// speedup vs baseline: 1.0151x; 1.0151x over previous
#include <cuda_runtime.h>
#include <cuda_fp16.h>
#include <stdint.h>

// ---------------------------------------------------------------------------
// TopK Router, R14: single-pass fp16 HMMA GEMM (R12 pipeline) with the exact
// contender re-ranking FUSED into the router as a per-block tail.
// 2 launches total (prep_W, router) -> ncu -s 5 captures the router again.
// logits = x @ W^T : [16384, 64], softmax, top-2.
// out f32: probs[16384*64] ++ indices[16384*2] ++ values[16384*2]
// ---------------------------------------------------------------------------

#define D_DIM   4096
#define E_DIM   64
#define NROWS   16384
#define ROWS_PER_BLK 128
#define THREADS 256
#define KC      64
#define NCHUNK  (D_DIM / KC)

#define GAP_T    4e-3f        // flag threshold (logit units)
#define BAND_L   6e-3f        // contender band below v2 (logit units)

// smem layout (bytes)
#define XS_SLOT   (ROWS_PER_BLK * 68 * 4)    // 34816 B
#define SM_XS(s)  ((s) * XS_SLOT)            // 3 slots
#define A_TILE    (ROWS_PER_BLK * 128)       // 16384 B
#define SM_A(b)   (3 * XS_SLOT + (b) * A_TILE)
#define W_TILE    (E_DIM * 128)              // 8192 B
#define SM_W(s)   (3 * XS_SLOT + 2 * A_TILE + (s) * W_TILE)   // 4 slots
#define SM_LIST   (3 * XS_SLOT + 2 * A_TILE + 4 * W_TILE)     // flag list
#define SMEM_BYTES (SM_LIST + 544)           // count + 128 ids + pad

#define LG_STRIDE 68                          // logits live in XS region

#define SWZ(o) ((o) ^ (((o) >> 3) & 0x70))

__device__ __half g_Whi[E_DIM * D_DIM];

// ---------------- PTX helpers -----------------------------------------------
__device__ __forceinline__ void cp16(uint32_t dst, const void* src) {
    asm volatile("cp.async.cg.shared.global [%0], [%1], 16;" :: "r"(dst), "l"(src));
}
__device__ __forceinline__ void cp_commit() {
    asm volatile("cp.async.commit_group;");
}
__device__ __forceinline__ void cp_wait1() {
    asm volatile("cp.async.wait_group 1;" ::: "memory");
}
__device__ __forceinline__ void cp_wait0() {
    asm volatile("cp.async.wait_group 0;" ::: "memory");
}
__device__ __forceinline__ void ldsm4(uint32_t addr, uint32_t* r) {
    asm volatile("ldmatrix.sync.aligned.m8n8.x4.shared.b16 {%0,%1,%2,%3}, [%4];"
                 : "=r"(r[0]), "=r"(r[1]), "=r"(r[2]), "=r"(r[3]) : "r"(addr));
}
__device__ __forceinline__ void mma16816(float* c,
                                         const uint32_t* a,
                                         uint32_t b0, uint32_t b1) {
    asm volatile(
        "mma.sync.aligned.m16n8k16.row.col.f32.f16.f16.f32 "
        "{%0,%1,%2,%3}, {%4,%5,%6,%7}, {%8,%9}, {%0,%1,%2,%3};"
        : "+f"(c[0]), "+f"(c[1]), "+f"(c[2]), "+f"(c[3])
        : "r"(a[0]), "r"(a[1]), "r"(a[2]), "r"(a[3]), "r"(b0), "r"(b1));
}

// ---------------- prep kernel -------------------------------------------------
__global__ void prep_W(const float* __restrict__ W) {
    int i = blockIdx.x * blockDim.x + threadIdx.x;
    g_Whi[i] = __float2half_rn(W[i] * 64.0f);
}

// ---------------- producer helpers (pt in [0,128)) ----------------------------
__device__ __forceinline__ void cpXW_chunk(uint32_t sbase, const float* __restrict__ x,
                                           int row0, int c, int pt) {
    const int slot  = c % 3;
    const int wslot = c % 4;
    const int c0 = c * KC;
#pragma unroll
    for (int it = 0; it < 16; ++it) {
        int id = it * 128 + pt;
        int row = id >> 4, seg = id & 15;
        uint32_t dst = sbase + SM_XS(slot) + (uint32_t)(row * 272 + seg * 16);
        cp16(dst, x + (size_t)(row0 + row) * D_DIM + c0 + seg * 4);
    }
#pragma unroll
    for (int it = 0; it < 4; ++it) {
        int id = it * 128 + pt;
        int e = id >> 3, q = id & 7;
        uint32_t dst = sbase + SM_W(wslot) + SWZ(e * 128 + q * 16);
        cp16(dst, g_Whi + (size_t)e * D_DIM + c0 + q * 8);
    }
    cp_commit();
}

__device__ __forceinline__ void convert_chunk(char* smem, int c, int pt) {
    const float* xs = (const float*)(smem + SM_XS(c % 3));
    char* dst = smem + SM_A(c & 1);
#pragma unroll
    for (int it = 0; it < 8; ++it) {
        int id = it * 128 + pt;
        int row = id >> 3, g = id & 7;
        const float* p = xs + row * 68 + g * 8;
        float4 a = *(const float4*)p;
        float4 b = *(const float4*)(p + 4);
        __half2 h0 = __floats2half2_rn(a.x * 16.0f, a.y * 16.0f);
        __half2 h1 = __floats2half2_rn(a.z * 16.0f, a.w * 16.0f);
        __half2 h2 = __floats2half2_rn(b.x * 16.0f, b.y * 16.0f);
        __half2 h3 = __floats2half2_rn(b.z * 16.0f, b.w * 16.0f);
        uint32_t off = SWZ(row * 128 + g * 16);
        *(uint4*)(dst + off) = make_uint4(
            *reinterpret_cast<uint32_t*>(&h0), *reinterpret_cast<uint32_t*>(&h1),
            *reinterpret_cast<uint32_t*>(&h2), *reinterpret_cast<uint32_t*>(&h3));
    }
}

// ---------------- main kernel -------------------------------------------------
__global__ void __launch_bounds__(THREADS, 1)
router_kernel(const float* __restrict__ x, const float* __restrict__ W,
              float* __restrict__ out)
{
    extern __shared__ char smem[];
    const int t    = threadIdx.x;
    const int lane = t & 31;
    const int row0 = blockIdx.x * ROWS_PER_BLK;
    const uint32_t sbase = (uint32_t)__cvta_generic_to_shared(smem);
    const bool consumer = (t < 128);

    int* flg_cnt  = (int*)(smem + SM_LIST);
    int* flg_list = flg_cnt + 1;

    const int lg = lane >> 3;
    const int li = lane & 7;

    const int wc = t >> 5;                    // 0..3 consumers, rows [32wc,+32)
    float acc[2][8][4];
#pragma unroll
    for (int m = 0; m < 2; ++m)
#pragma unroll
        for (int j = 0; j < 8; ++j)
#pragma unroll
            for (int q = 0; q < 4; ++q) acc[m][j][q] = 0.f;

    uint32_t aoffb[2];
#pragma unroll
    for (int m = 0; m < 2; ++m) {
        int arow = 32 * wc + 16 * m + li + ((lg & 1) ? 8 : 0);
        aoffb[m] = (uint32_t)(arow * 128 + ((lg & 2) ? 16 : 0));
    }
    const int berow = li + ((lg & 2) ? 8 : 0);
    const uint32_t boffb = (uint32_t)(berow * 128 + ((lg & 1) ? 16 : 0));

    const int pt = t - 128;

    if (t == 0) *flg_cnt = 0;

    // ---- prologue (producers) ----
    if (!consumer) {
        cpXW_chunk(sbase, x, row0, 0, pt);   // G0
        cpXW_chunk(sbase, x, row0, 1, pt);   // G1
        cp_wait1();                          // G0 done
    }
    __syncthreads();
    if (!consumer) {
        convert_chunk(smem, 0, pt);          // A0
        cpXW_chunk(sbase, x, row0, 2, pt);   // G2
        cp_wait1();                          // G1 done
    }
    __syncthreads();

    // ---- main loop ----
    for (int c = 0; c < NCHUNK; ++c) {
        if (consumer) {
            const uint32_t ahi = sbase + SM_A(c & 1);
            const uint32_t whi = sbase + SM_W(c % 4);

            uint32_t fw[2][4][4];
#pragma unroll
            for (int p = 0; p < 4; ++p)
                ldsm4(whi + SWZ(boffb + (uint32_t)(p * 16 * 128)), fw[0][p]);
#pragma unroll
            for (int s = 0; s < 4; ++s) {
                uint32_t fa[2][4];
#pragma unroll
                for (int m = 0; m < 2; ++m)
                    ldsm4(ahi + SWZ(aoffb[m] + s * 32), fa[m]);
                if (s < 3) {
#pragma unroll
                    for (int p = 0; p < 4; ++p)
                        ldsm4(whi + SWZ(boffb + (uint32_t)(p * 16 * 128) + (s + 1) * 32),
                              fw[(s + 1) & 1][p]);
                }
#pragma unroll
                for (int p = 0; p < 4; ++p) {
                    const uint32_t* bh = fw[s & 1][p];
#pragma unroll
                    for (int m = 0; m < 2; ++m) {
                        mma16816(acc[m][2 * p],     fa[m], bh[0], bh[1]);
                        mma16816(acc[m][2 * p + 1], fa[m], bh[2], bh[3]);
                    }
                }
            }
        } else {
            if (c + 1 < NCHUNK) convert_chunk(smem, c + 1, pt);
            if (c + 3 < NCHUNK) {
                cpXW_chunk(sbase, x, row0, c + 3, pt);
                cp_wait1();
            } else {
                cp_wait0();
            }
        }
        __syncthreads();
    }

    // ---- logits -> smem (reuse XS region) ----
    float* lgm = (float*)smem;
    if (consumer) {
        const int r_in = lane >> 2;
        const int col  = 2 * (lane & 3);
        const float sc = 1.0f / 1024.0f;
#pragma unroll
        for (int m = 0; m < 2; ++m) {
            const int rb = 32 * wc + 16 * m + r_in;
#pragma unroll
            for (int j = 0; j < 8; ++j) {
                *(float2*)(lgm + rb * LG_STRIDE + 8 * j + col)
                    = make_float2(acc[m][j][0] * sc, acc[m][j][1] * sc);
                *(float2*)(lgm + (rb + 8) * LG_STRIDE + 8 * j + col)
                    = make_float2(acc[m][j][2] * sc, acc[m][j][3] * sc);
            }
        }
    }
    __syncthreads();

    // ---- per-row softmax + top-2 + flagging ----
    if (t < ROWS_PER_BLK) {
        float l[64];
#pragma unroll
        for (int j = 0; j < 16; ++j) {
            float4 v = *(const float4*)(lgm + t * LG_STRIDE + 4 * j);
            l[4*j+0] = v.x; l[4*j+1] = v.y; l[4*j+2] = v.z; l[4*j+3] = v.w;
        }

        float mx = l[0];
#pragma unroll
        for (int j = 1; j < 64; ++j) mx = fmaxf(mx, l[j]);

        float v1 = -3.4e38f, v2 = -3.4e38f, v3 = -3.4e38f;
        int   i1 = 0,        i2 = 0;
#pragma unroll
        for (int j = 0; j < 64; ++j) {
            float lj = l[j];
            if (lj > v1)      { v3 = v2; v2 = v1; i2 = i1; v1 = lj; i1 = j; }
            else if (lj > v2) { v3 = v2; v2 = lj; i2 = j; }
            else if (lj > v3) { v3 = lj; }
        }

        float p[64], s = 0.f;
#pragma unroll
        for (int j = 0; j < 64; ++j) { p[j] = __expf(l[j] - mx); s += p[j]; }
        float inv = __fdividef(1.0f, s);

        const int grow = row0 + t;
        float* po = out + (size_t)grow * 64;
#pragma unroll
        for (int j = 0; j < 16; ++j) {
            float4 v;
            v.x = p[4*j+0] * inv; v.y = p[4*j+1] * inv;
            v.z = p[4*j+2] * inv; v.w = p[4*j+3] * inv;
            *(float4*)(po + 4 * j) = v;
        }
        float* io = out + (size_t)NROWS * 64;
        io[(size_t)grow * 2 + 0] = (float)i1;
        io[(size_t)grow * 2 + 1] = (float)i2;
        float* vo = out + (size_t)NROWS * 64 + (size_t)NROWS * 2;
        vo[(size_t)grow * 2 + 0] = __expf(v1 - mx) * inv;
        vo[(size_t)grow * 2 + 1] = __expf(v2 - mx) * inv;

        if ((v1 - v2) < GAP_T || (v2 - v3) < GAP_T) {
            int slot = atomicAdd(flg_cnt, 1);
            flg_list[slot] = t;               // local row id
        }
    }
    __syncthreads();   // flags + probs (global, same block) visible

    // ---- fused fixup: one warp per flagged row ----
    const int nflag = *flg_cnt;
    const int wid   = t >> 5;                 // 0..7
    for (int ci = wid; ci < nflag; ci += 8) {
        const int lrow = flg_list[ci];
        const int row  = row0 + lrow;
        const float* lr = lgm + lrow * LG_STRIDE;

        float l0 = lr[lane];
        float l1 = lr[lane + 32];

        // warp top-2 of logits (values only)
        float m1 = fmaxf(l0, l1), m2 = fminf(l0, l1);
#pragma unroll
        for (int o = 16; o > 0; o >>= 1) {
            float o1 = __shfl_xor_sync(0xFFFFFFFF, m1, o);
            float o2 = __shfl_xor_sync(0xFFFFFFFF, m2, o);
            float n1 = fmaxf(m1, o1);
            float n2 = fminf(fmaxf(m1, o2), fmaxf(o1, m2));
            n2 = fmaxf(n2, fminf(m1, o1));
            m1 = n1; m2 = n2;
        }
        const float thresh = m2 - BAND_L;

        unsigned b0 = __ballot_sync(0xFFFFFFFF, l0 >= thresh);
        unsigned b1 = __ballot_sync(0xFFFFFFFF, l1 >= thresh);

        const float4* xr = (const float4*)(x + (size_t)row * D_DIM);

        float best1 = -3.4e38f, best2 = -3.4e38f;
        int   bi1 = -1,         bi2 = -1;

        for (int e = 0; e < 64; ++e) {
            bool cand = (e < 32) ? ((b0 >> e) & 1u) : ((b1 >> (e - 32)) & 1u);
            if (!cand) continue;   // warp-uniform (ballot)
            const float4* wr = (const float4*)(W + (size_t)e * D_DIM);
            float a0 = 0.f, a1 = 0.f;
            for (int i = lane; i < D_DIM / 4; i += 64) {
                float4 xv = xr[i],      wv = wr[i];
                float4 xu = xr[i + 32], wu = wr[i + 32];
                a0 += xv.x * wv.x; a0 += xv.y * wv.y;
                a0 += xv.z * wv.z; a0 += xv.w * wv.w;
                a1 += xu.x * wu.x; a1 += xu.y * wu.y;
                a1 += xu.z * wu.z; a1 += xu.w * wu.w;
            }
            float a = a0 + a1;
#pragma unroll
            for (int o = 16; o > 0; o >>= 1)
                a += __shfl_xor_sync(0xFFFFFFFF, a, o);
            // ascending e + strict > = lowest-index tie-break (matches jax)
            if (a > best1)      { best2 = best1; bi2 = bi1; best1 = a; bi1 = e; }
            else if (a > best2) { best2 = a; bi2 = e; }
        }

        if (lane == 0) {
            const float* probs = out + (size_t)row * 64;
            float* io = out + (size_t)NROWS * 64;
            io[(size_t)row * 2 + 0] = (float)bi1;
            io[(size_t)row * 2 + 1] = (float)bi2;
            float* vo = out + (size_t)NROWS * 64 + (size_t)NROWS * 2;
            vo[(size_t)row * 2 + 0] = probs[bi1];
            vo[(size_t)row * 2 + 1] = probs[bi2];
        }
    }
}

// ---------------------------------------------------------------------------
extern "C" void kernel_launch(void* const* d_in, const int* in_sizes, int n_in,
                              void* d_out, int out_size) {
    const float* x = (const float*)d_in[0];
    const float* W = (const float*)d_in[1];
    float* out = (float*)d_out;

    prep_W<<<(E_DIM * D_DIM) / 256, 256>>>(W);

    cudaFuncSetAttribute(router_kernel,
                         cudaFuncAttributeMaxDynamicSharedMemorySize, SMEM_BYTES);
    router_kernel<<<NROWS / ROWS_PER_BLK, THREADS, SMEM_BYTES>>>(x, W, out);
}

// round 15
// speedup vs baseline: 1.1477x; 1.1306x over previous
#include <cuda_runtime.h>
#include <cuda_fp16.h>
#include <stdint.h>

// ---------------------------------------------------------------------------
// TopK Router, R15: 64 rows/CTA, 256 CTAs -> 2 CTAs per SM so independently
// synchronized CTAs hide each other's barrier/latency stalls (R14 profile
// showed issue=19%, all units <50% => latency-bound, not throughput-bound).
// Single-pass fp16 HMMA + fused exact contender re-ranking.
// out f32: probs[16384*64] ++ indices[16384*2] ++ values[16384*2]
// ---------------------------------------------------------------------------

#define D_DIM   4096
#define E_DIM   64
#define NROWS   16384
#define ROWS_PER_BLK 64
#define THREADS 256
#define KC      64
#define NCHUNK  (D_DIM / KC)
#define GRID    (NROWS / ROWS_PER_BLK)       // 256

#define GAP_T    4e-3f
#define BAND_L   6e-3f

// smem layout (bytes)
#define XS_SLOT   (ROWS_PER_BLK * 68 * 4)    // 17408 B
#define SM_XS(s)  ((s) * XS_SLOT)            // 3 slots: 52224
#define A_TILE    (ROWS_PER_BLK * 128)       // 8192 B
#define SM_A(b)   (3 * XS_SLOT + (b) * A_TILE)
#define W_TILE    (E_DIM * 128)              // 8192 B
#define SM_W(s)   (3 * XS_SLOT + 2 * A_TILE + (s) * W_TILE)   // 4 slots
#define SM_LIST   (3 * XS_SLOT + 2 * A_TILE + 4 * W_TILE)     // 101376
#define SMEM_BYTES (SM_LIST + 272)           // ~101648 -> 2 CTAs/SM fit

#define LG_STRIDE 68

#define SWZ(o) ((o) ^ (((o) >> 3) & 0x70))

__device__ __half g_Whi[E_DIM * D_DIM];

// ---------------- PTX helpers -----------------------------------------------
__device__ __forceinline__ void cp16(uint32_t dst, const void* src) {
    asm volatile("cp.async.cg.shared.global [%0], [%1], 16;" :: "r"(dst), "l"(src));
}
__device__ __forceinline__ void cp_commit() {
    asm volatile("cp.async.commit_group;");
}
__device__ __forceinline__ void cp_wait1() {
    asm volatile("cp.async.wait_group 1;" ::: "memory");
}
__device__ __forceinline__ void cp_wait0() {
    asm volatile("cp.async.wait_group 0;" ::: "memory");
}
__device__ __forceinline__ void ldsm4(uint32_t addr, uint32_t* r) {
    asm volatile("ldmatrix.sync.aligned.m8n8.x4.shared.b16 {%0,%1,%2,%3}, [%4];"
                 : "=r"(r[0]), "=r"(r[1]), "=r"(r[2]), "=r"(r[3]) : "r"(addr));
}
__device__ __forceinline__ void mma16816(float* c,
                                         const uint32_t* a,
                                         uint32_t b0, uint32_t b1) {
    asm volatile(
        "mma.sync.aligned.m16n8k16.row.col.f32.f16.f16.f32 "
        "{%0,%1,%2,%3}, {%4,%5,%6,%7}, {%8,%9}, {%0,%1,%2,%3};"
        : "+f"(c[0]), "+f"(c[1]), "+f"(c[2]), "+f"(c[3])
        : "r"(a[0]), "r"(a[1]), "r"(a[2]), "r"(a[3]), "r"(b0), "r"(b1));
}

// ---------------- prep kernel -------------------------------------------------
__global__ void prep_W(const float* __restrict__ W) {
    int i = blockIdx.x * blockDim.x + threadIdx.x;
    g_Whi[i] = __float2half_rn(W[i] * 64.0f);
}

// ---------------- producer helpers (pt in [0,128)) ----------------------------
__device__ __forceinline__ void cpXW_chunk(uint32_t sbase, const float* __restrict__ x,
                                           int row0, int c, int pt) {
    const int slot  = c % 3;
    const int wslot = c % 4;
    const int c0 = c * KC;
    // x: 64 rows x 64 f32 = 1024 x 16B, 8 per thread
#pragma unroll
    for (int it = 0; it < 8; ++it) {
        int id = it * 128 + pt;
        int row = id >> 4, seg = id & 15;
        uint32_t dst = sbase + SM_XS(slot) + (uint32_t)(row * 272 + seg * 16);
        cp16(dst, x + (size_t)(row0 + row) * D_DIM + c0 + seg * 4);
    }
    // W: 64 e x 64 k fp16 = 512 x 16B, 4 per thread
#pragma unroll
    for (int it = 0; it < 4; ++it) {
        int id = it * 128 + pt;
        int e = id >> 3, q = id & 7;
        uint32_t dst = sbase + SM_W(wslot) + SWZ(e * 128 + q * 16);
        cp16(dst, g_Whi + (size_t)e * D_DIM + c0 + q * 8);
    }
    cp_commit();
}

__device__ __forceinline__ void convert_chunk(char* smem, int c, int pt) {
    const float* xs = (const float*)(smem + SM_XS(c % 3));
    char* dst = smem + SM_A(c & 1);
    // 64 rows x 8 groups = 512 items, 4 per thread
#pragma unroll
    for (int it = 0; it < 4; ++it) {
        int id = it * 128 + pt;
        int row = id >> 3, g = id & 7;
        const float* p = xs + row * 68 + g * 8;
        float4 a = *(const float4*)p;
        float4 b = *(const float4*)(p + 4);
        __half2 h0 = __floats2half2_rn(a.x * 16.0f, a.y * 16.0f);
        __half2 h1 = __floats2half2_rn(a.z * 16.0f, a.w * 16.0f);
        __half2 h2 = __floats2half2_rn(b.x * 16.0f, b.y * 16.0f);
        __half2 h3 = __floats2half2_rn(b.z * 16.0f, b.w * 16.0f);
        uint32_t off = SWZ(row * 128 + g * 16);
        *(uint4*)(dst + off) = make_uint4(
            *reinterpret_cast<uint32_t*>(&h0), *reinterpret_cast<uint32_t*>(&h1),
            *reinterpret_cast<uint32_t*>(&h2), *reinterpret_cast<uint32_t*>(&h3));
    }
}

// ---------------- main kernel -------------------------------------------------
__global__ void __launch_bounds__(THREADS, 2)
router_kernel(const float* __restrict__ x, const float* __restrict__ W,
              float* __restrict__ out)
{
    extern __shared__ char smem[];
    const int t    = threadIdx.x;
    const int lane = t & 31;
    const int row0 = blockIdx.x * ROWS_PER_BLK;
    const uint32_t sbase = (uint32_t)__cvta_generic_to_shared(smem);
    const bool consumer = (t < 128);

    int* flg_cnt  = (int*)(smem + SM_LIST);
    int* flg_list = flg_cnt + 1;

    const int lg = lane >> 3;
    const int li = lane & 7;

    // consumer warp wc (0..3): rows [16wc, 16wc+16) x 64 experts
    const int wc = t >> 5;
    float acc[8][4];
#pragma unroll
    for (int j = 0; j < 8; ++j)
#pragma unroll
        for (int q = 0; q < 4; ++q) acc[j][q] = 0.f;

    const int arow = 16 * wc + li + ((lg & 1) ? 8 : 0);
    const uint32_t aoffb = (uint32_t)(arow * 128 + ((lg & 2) ? 16 : 0));
    const int berow = li + ((lg & 2) ? 8 : 0);
    const uint32_t boffb = (uint32_t)(berow * 128 + ((lg & 1) ? 16 : 0));

    const int pt = t - 128;

    if (t == 0) *flg_cnt = 0;

    // ---- prologue (producers) ----
    if (!consumer) {
        cpXW_chunk(sbase, x, row0, 0, pt);
        cpXW_chunk(sbase, x, row0, 1, pt);
        cp_wait1();
    }
    __syncthreads();
    if (!consumer) {
        convert_chunk(smem, 0, pt);
        cpXW_chunk(sbase, x, row0, 2, pt);
        cp_wait1();
    }
    __syncthreads();

    // ---- main loop ----
    for (int c = 0; c < NCHUNK; ++c) {
        if (consumer) {
            const uint32_t ahi = sbase + SM_A(c & 1);
            const uint32_t whi = sbase + SM_W(c % 4);

            uint32_t fw[2][4][4];
#pragma unroll
            for (int p = 0; p < 4; ++p)
                ldsm4(whi + SWZ(boffb + (uint32_t)(p * 16 * 128)), fw[0][p]);
#pragma unroll
            for (int s = 0; s < 4; ++s) {
                uint32_t fa[4];
                ldsm4(ahi + SWZ(aoffb + s * 32), fa);
                if (s < 3) {
#pragma unroll
                    for (int p = 0; p < 4; ++p)
                        ldsm4(whi + SWZ(boffb + (uint32_t)(p * 16 * 128) + (s + 1) * 32),
                              fw[(s + 1) & 1][p]);
                }
#pragma unroll
                for (int p = 0; p < 4; ++p) {
                    const uint32_t* bh = fw[s & 1][p];
                    mma16816(acc[2 * p],     fa, bh[0], bh[1]);
                    mma16816(acc[2 * p + 1], fa, bh[2], bh[3]);
                }
            }
        } else {
            if (c + 1 < NCHUNK) convert_chunk(smem, c + 1, pt);
            if (c + 3 < NCHUNK) {
                cpXW_chunk(sbase, x, row0, c + 3, pt);
                cp_wait1();
            } else {
                cp_wait0();
            }
        }
        __syncthreads();
    }

    // ---- logits -> smem (reuse XS region) ----
    float* lgm = (float*)smem;
    if (consumer) {
        const int r_in = lane >> 2;
        const int col  = 2 * (lane & 3);
        const float sc = 1.0f / 1024.0f;
        const int rb = 16 * wc + r_in;
#pragma unroll
        for (int j = 0; j < 8; ++j) {
            *(float2*)(lgm + rb * LG_STRIDE + 8 * j + col)
                = make_float2(acc[j][0] * sc, acc[j][1] * sc);
            *(float2*)(lgm + (rb + 8) * LG_STRIDE + 8 * j + col)
                = make_float2(acc[j][2] * sc, acc[j][3] * sc);
        }
    }
    __syncthreads();

    // ---- per-row softmax + top-2 + flagging ----
    if (t < ROWS_PER_BLK) {
        float l[64];
#pragma unroll
        for (int j = 0; j < 16; ++j) {
            float4 v = *(const float4*)(lgm + t * LG_STRIDE + 4 * j);
            l[4*j+0] = v.x; l[4*j+1] = v.y; l[4*j+2] = v.z; l[4*j+3] = v.w;
        }

        float mx = l[0];
#pragma unroll
        for (int j = 1; j < 64; ++j) mx = fmaxf(mx, l[j]);

        float v1 = -3.4e38f, v2 = -3.4e38f, v3 = -3.4e38f;
        int   i1 = 0,        i2 = 0;
#pragma unroll
        for (int j = 0; j < 64; ++j) {
            float lj = l[j];
            if (lj > v1)      { v3 = v2; v2 = v1; i2 = i1; v1 = lj; i1 = j; }
            else if (lj > v2) { v3 = v2; v2 = lj; i2 = j; }
            else if (lj > v3) { v3 = lj; }
        }

        float p[64], s = 0.f;
#pragma unroll
        for (int j = 0; j < 64; ++j) { p[j] = __expf(l[j] - mx); s += p[j]; }
        float inv = __fdividef(1.0f, s);

        const int grow = row0 + t;
        float* po = out + (size_t)grow * 64;
#pragma unroll
        for (int j = 0; j < 16; ++j) {
            float4 v;
            v.x = p[4*j+0] * inv; v.y = p[4*j+1] * inv;
            v.z = p[4*j+2] * inv; v.w = p[4*j+3] * inv;
            *(float4*)(po + 4 * j) = v;
        }
        float* io = out + (size_t)NROWS * 64;
        io[(size_t)grow * 2 + 0] = (float)i1;
        io[(size_t)grow * 2 + 1] = (float)i2;
        float* vo = out + (size_t)NROWS * 64 + (size_t)NROWS * 2;
        vo[(size_t)grow * 2 + 0] = __expf(v1 - mx) * inv;
        vo[(size_t)grow * 2 + 1] = __expf(v2 - mx) * inv;

        if ((v1 - v2) < GAP_T || (v2 - v3) < GAP_T) {
            int slot = atomicAdd(flg_cnt, 1);
            flg_list[slot] = t;
        }
    }
    __syncthreads();

    // ---- fused fixup: one warp per flagged row ----
    const int nflag = *flg_cnt;
    const int wid   = t >> 5;                 // 0..7
    for (int ci = wid; ci < nflag; ci += 8) {
        const int lrow = flg_list[ci];
        const int row  = row0 + lrow;
        const float* lr = lgm + lrow * LG_STRIDE;

        float l0 = lr[lane];
        float l1 = lr[lane + 32];

        float m1 = fmaxf(l0, l1), m2 = fminf(l0, l1);
#pragma unroll
        for (int o = 16; o > 0; o >>= 1) {
            float o1 = __shfl_xor_sync(0xFFFFFFFF, m1, o);
            float o2 = __shfl_xor_sync(0xFFFFFFFF, m2, o);
            float n1 = fmaxf(m1, o1);
            float n2 = fminf(fmaxf(m1, o2), fmaxf(o1, m2));
            n2 = fmaxf(n2, fminf(m1, o1));
            m1 = n1; m2 = n2;
        }
        const float thresh = m2 - BAND_L;

        unsigned b0 = __ballot_sync(0xFFFFFFFF, l0 >= thresh);
        unsigned b1 = __ballot_sync(0xFFFFFFFF, l1 >= thresh);

        const float4* xr = (const float4*)(x + (size_t)row * D_DIM);

        float best1 = -3.4e38f, best2 = -3.4e38f;
        int   bi1 = -1,         bi2 = -1;

        for (int e = 0; e < 64; ++e) {
            bool cand = (e < 32) ? ((b0 >> e) & 1u) : ((b1 >> (e - 32)) & 1u);
            if (!cand) continue;
            const float4* wr = (const float4*)(W + (size_t)e * D_DIM);
            float a0 = 0.f, a1 = 0.f;
            for (int i = lane; i < D_DIM / 4; i += 64) {
                float4 xv = xr[i],      wv = wr[i];
                float4 xu = xr[i + 32], wu = wr[i + 32];
                a0 += xv.x * wv.x; a0 += xv.y * wv.y;
                a0 += xv.z * wv.z; a0 += xv.w * wv.w;
                a1 += xu.x * wu.x; a1 += xu.y * wu.y;
                a1 += xu.z * wu.z; a1 += xu.w * wu.w;
            }
            float a = a0 + a1;
#pragma unroll
            for (int o = 16; o > 0; o >>= 1)
                a += __shfl_xor_sync(0xFFFFFFFF, a, o);
            if (a > best1)      { best2 = best1; bi2 = bi1; best1 = a; bi1 = e; }
            else if (a > best2) { best2 = a; bi2 = e; }
        }

        if (lane == 0) {
            const float* probs = out + (size_t)row * 64;
            float* io = out + (size_t)NROWS * 64;
            io[(size_t)row * 2 + 0] = (float)bi1;
            io[(size_t)row * 2 + 1] = (float)bi2;
            float* vo = out + (size_t)NROWS * 64 + (size_t)NROWS * 2;
            vo[(size_t)row * 2 + 0] = probs[bi1];
            vo[(size_t)row * 2 + 1] = probs[bi2];
        }
    }
}

// ---------------------------------------------------------------------------
extern "C" void kernel_launch(void* const* d_in, const int* in_sizes, int n_in,
                              void* d_out, int out_size) {
    const float* x = (const float*)d_in[0];
    const float* W = (const float*)d_in[1];
    float* out = (float*)d_out;

    prep_W<<<(E_DIM * D_DIM) / 256, 256>>>(W);

    cudaFuncSetAttribute(router_kernel,
                         cudaFuncAttributeMaxDynamicSharedMemorySize, SMEM_BYTES);
    router_kernel<<<GRID, THREADS, SMEM_BYTES>>>(x, W, out);
}